// round 12
// baseline (speedup 1.0000x reference)
#include <cuda_runtime.h>
#include <cuda_bf16.h>
#include <math.h>
#include <cstdint>

#define Bsz   32
#define Tn    1024
#define Cn    512
#define LMAX  4096
#define BT    (Bsz * Tn)

// ---------------------------------------------------------------------------
// Scratch (allocation-free rule: device globals)
// ---------------------------------------------------------------------------
__device__ float g_buf1[(size_t)BT * Cn];             // conv output
__device__ __nv_bfloat16 g_xhi[(size_t)BT * Cn];      // activation hi
__device__ __nv_bfloat16 g_xlo[(size_t)BT * Cn];      // activation lo
__device__ __nv_bfloat16 g_whi[2][3 * 512 * 512];     // weights hi, [conv][tap][n][ci]
__device__ __nv_bfloat16 g_wlo[2][3 * 512 * 512];     // weights lo
__device__ int   g_idx[Bsz * LMAX];                   // frame -> token LUT
__device__ int   g_total[Bsz];

// ---------------------------------------------------------------------------
// Helpers
// ---------------------------------------------------------------------------
__device__ __forceinline__ uint32_t smem_u32(const void* p) {
    uint32_t a;
    asm("{ .reg .u64 t; cvta.to.shared.u64 t, %1; cvt.u32.u64 %0, t; }" : "=r"(a) : "l"(p));
    return a;
}
__device__ __forceinline__ void cp_async16(uint32_t dst, const void* src) {
    asm volatile("cp.async.ca.shared.global [%0], [%1], 16;" :: "r"(dst), "l"(src) : "memory");
}
__device__ __forceinline__ void cp_async16z(uint32_t dst, const void* src, int sz) {
    asm volatile("cp.async.ca.shared.global [%0], [%1], 16, %2;" :: "r"(dst), "l"(src), "r"(sz) : "memory");
}
#define CP_COMMIT() asm volatile("cp.async.commit_group;" ::: "memory")
#define CP_WAIT0()  asm volatile("cp.async.wait_group 0;" ::: "memory")

__device__ __forceinline__ void ldsm_x4(uint32_t* r, uint32_t addr) {
    asm volatile("ldmatrix.sync.aligned.m8n8.x4.shared.b16 {%0,%1,%2,%3}, [%4];"
        : "=r"(r[0]), "=r"(r[1]), "=r"(r[2]), "=r"(r[3]) : "r"(addr));
}

__device__ __forceinline__ void mma16816(float* d, const uint32_t* a, const uint32_t* b) {
    asm volatile(
        "mma.sync.aligned.m16n8k16.row.col.f32.bf16.bf16.f32 "
        "{%0,%1,%2,%3}, {%4,%5,%6,%7}, {%8,%9}, {%0,%1,%2,%3};"
        : "+f"(d[0]), "+f"(d[1]), "+f"(d[2]), "+f"(d[3])
        : "r"(a[0]), "r"(a[1]), "r"(a[2]), "r"(a[3]), "r"(b[0]), "r"(b[1]));
}

__device__ __forceinline__ uint32_t pack_hi(float f0, float f1, uint32_t& lo_out) {
    __nv_bfloat16 h0 = __float2bfloat16(f0);
    __nv_bfloat16 h1 = __float2bfloat16(f1);
    float l0f = f0 - __bfloat162float(h0);
    float l1f = f1 - __bfloat162float(h1);
    __nv_bfloat16 l0 = __float2bfloat16(l0f);
    __nv_bfloat16 l1 = __float2bfloat16(l1f);
    unsigned short u0 = *reinterpret_cast<unsigned short*>(&h0);
    unsigned short u1 = *reinterpret_cast<unsigned short*>(&h1);
    unsigned short w0 = *reinterpret_cast<unsigned short*>(&l0);
    unsigned short w1 = *reinterpret_cast<unsigned short*>(&l1);
    lo_out = (uint32_t)w0 | ((uint32_t)w1 << 16);
    return (uint32_t)u0 | ((uint32_t)u1 << 16);
}

// ---------------------------------------------------------------------------
// Combined prep: blocks [0, XBLK) split activations, [XBLK, XBLK+WBLK) split
// both conv weights into hi/lo bf16 ([tap][n][ci] layout).
// ---------------------------------------------------------------------------
#define XBLK 8192                     // BT*Cn / (256*8)
#define WBLK 6144                     // 2*3*512*512 / 256
__global__ __launch_bounds__(256) void prep(const float* __restrict__ x,
                                            const int* __restrict__ tlen,
                                            const float* __restrict__ w1s,
                                            const float* __restrict__ w2s,
                                            __nv_bfloat16* __restrict__ xh,
                                            __nv_bfloat16* __restrict__ xl)
{
    if (blockIdx.x < XBLK) {
        size_t i = ((size_t)blockIdx.x * 256 + threadIdx.x) * 8;
        int row = (int)(i >> 9);
        int b = row >> 10, t = row & 1023;
        if (t > __ldg(&tlen[b]) + 2) return;
        float4 v0 = *(const float4*)(x + i);
        float4 v1 = *(const float4*)(x + i + 4);
        const float f[8] = {v0.x, v0.y, v0.z, v0.w, v1.x, v1.y, v1.z, v1.w};
        uint32_t hw[4], lw[4];
#pragma unroll
        for (int j = 0; j < 4; j++) hw[j] = pack_hi(f[2 * j], f[2 * j + 1], lw[j]);
        *(uint4*)(xh + i) = make_uint4(hw[0], hw[1], hw[2], hw[3]);
        *(uint4*)(xl + i) = make_uint4(lw[0], lw[1], lw[2], lw[3]);
    } else {
        int i = (blockIdx.x - XBLK) * 256 + threadIdx.x;
        int cv = i >= 512 * 512 * 3;
        int j = cv ? i - 512 * 512 * 3 : i;
        const float* w = cv ? w2s : w1s;
        int n = j / 1536, rem = j % 1536, ci = rem / 3, k = rem % 3;
        float v = w[j];
        __nv_bfloat16 h = __float2bfloat16(v);
        float hf = __bfloat162float(h);
        __nv_bfloat16 l = __float2bfloat16(v - hf);
        size_t o = ((size_t)k * 512 + n) * 512 + ci;
        g_whi[cv][o] = h;
        g_wlo[cv][o] = l;
    }
}

// ---------------------------------------------------------------------------
// Conv1d(512,512,K=3,SAME) via ldmatrix + HMMA bf16 3-pass split.
// Block tile 128x256, BK=64 (stride-144 smem rows, conflict-free), 512 thr.
// 2-stage cp.async pipeline. Tiles with t0 > len + skip_off skip conv work.
// When outp != null, each CTA also handles a 256-row slice of the duration-
// regulator gather (skipped CTAs do it immediately -> overlap; working CTAs
// append it after the epilogue, filling wave-tail bubbles).
// ---------------------------------------------------------------------------
#define BM 128
#define BN 256
#define NCH 24
#define AST 18432                    // 128 rows * 144B
#define BST 36864                    // 256 rows * 144B
#define STAGE (2 * AST + 2 * BST)    // 110592
#define SMEM_TOT (2 * STAGE)         // 221184

__global__ __launch_bounds__(512) void conv_tc(const __nv_bfloat16* __restrict__ xh,
                                               const __nv_bfloat16* __restrict__ xl,
                                               const __nv_bfloat16* __restrict__ wh,
                                               const __nv_bfloat16* __restrict__ wl,
                                               const float* __restrict__ bias,
                                               const int* __restrict__ tlen,
                                               int skip_off,
                                               float* __restrict__ y,
                                               const float* __restrict__ batch,
                                               float* __restrict__ outp)
{
    extern __shared__ char smc[];
    const int tid = threadIdx.x, wid = tid >> 5, lane = tid & 31;
    const int wm = wid & 3, wn = wid >> 2;
    const int g = lane >> 2, tg = lane & 3;
    const int n0 = blockIdx.x * BN;
    const int m0 = blockIdx.y * BM;
    const int b = m0 >> 10, t0 = m0 & 1023;

    const int len = __ldg(&tlen[b]);
    const bool do_conv = (t0 <= len + skip_off);

    if (do_conv) {
        float acc[2][8][4];
#pragma unroll
        for (int mt = 0; mt < 2; mt++)
#pragma unroll
            for (int nt = 0; nt < 8; nt++)
#pragma unroll
                for (int j = 0; j < 4; j++) acc[mt][nt][j] = 0.f;

#define ISSUE(ch, stg) do {                                                           \
    int tau = (ch) >> 3, ci0 = ((ch) & 7) * 64;                                       \
    char* S = smc + (stg) * STAGE;                                                    \
    _Pragma("unroll")                                                                 \
    for (int q = 0; q < 4; q++) {                                                     \
        int t = tid + q * 512;                                                        \
        int comp = t >> 10, rem = t & 1023, row = rem >> 3, seg = rem & 7;            \
        int tt = t0 + row + tau - 1;                                                  \
        int tc = tt < 0 ? 0 : (tt > 1023 ? 1023 : tt);                                \
        const __nv_bfloat16* src = (comp ? xl : xh) +                                 \
            ((size_t)(b << 10) + tc) * 512 + ci0 + seg * 8;                           \
        int sz = ((unsigned)tt < 1024u) ? 16 : 0;                                     \
        cp_async16z(smem_u32(S + comp * AST + row * 144 + seg * 16), src, sz);        \
    }                                                                                 \
    _Pragma("unroll")                                                                 \
    for (int q = 0; q < 8; q++) {                                                     \
        int t = tid + q * 512;                                                        \
        int comp = t >> 11, rem = t & 2047, row = rem >> 3, seg = rem & 7;            \
        const __nv_bfloat16* src = (comp ? wl : wh) +                                 \
            ((size_t)(tau * 512 + n0 + row)) * 512 + ci0 + seg * 8;                   \
        cp_async16(smem_u32(S + 2 * AST + comp * BST + row * 144 + seg * 16), src);   \
    }                                                                                 \
    CP_COMMIT();                                                                      \
} while (0)

        ISSUE(0, 0);

        const uint32_t a_row = (uint32_t)(wm * 32 + (lane & 15));
        const uint32_t a_koff = (uint32_t)((lane >> 4) * 16);
        const uint32_t b_row = (uint32_t)(wn * 64 + (lane & 7) + ((lane >> 4) * 8));
        const uint32_t b_koff = (uint32_t)(((lane >> 3) & 1) * 16);

        for (int ch = 0; ch < NCH; ch++) {
            CP_WAIT0();
            __syncthreads();
            if (ch + 1 < NCH) ISSUE(ch + 1, (ch + 1) & 1);

            char* S = smc + (ch & 1) * STAGE;
            char* Ah = S;
            char* Al = S + AST;
            char* Bh = S + 2 * AST;
            char* Bl = S + 2 * AST + BST;

#pragma unroll
            for (int kk2 = 0; kk2 < 4; kk2++) {
                const int kb = kk2 * 32;
                uint32_t ah[2][4], al[2][4], bh[8][2], bl[8][2];
#pragma unroll
                for (int mt = 0; mt < 2; mt++) {
                    uint32_t off = (a_row + mt * 16) * 144 + a_koff + kb;
                    ldsm_x4(ah[mt], smem_u32(Ah + off));
                    ldsm_x4(al[mt], smem_u32(Al + off));
                }
#pragma unroll
                for (int p = 0; p < 4; p++) {
                    uint32_t off = (b_row + p * 16) * 144 + b_koff + kb;
                    uint32_t r[4];
                    ldsm_x4(r, smem_u32(Bh + off));
                    bh[2 * p][0] = r[0]; bh[2 * p][1] = r[1];
                    bh[2 * p + 1][0] = r[2]; bh[2 * p + 1][1] = r[3];
                    ldsm_x4(r, smem_u32(Bl + off));
                    bl[2 * p][0] = r[0]; bl[2 * p][1] = r[1];
                    bl[2 * p + 1][0] = r[2]; bl[2 * p + 1][1] = r[3];
                }
#pragma unroll
                for (int nt = 0; nt < 8; nt++)
#pragma unroll
                    for (int mt = 0; mt < 2; mt++)
                        mma16816(acc[mt][nt], ah[mt], bh[nt]);
#pragma unroll
                for (int nt = 0; nt < 8; nt++)
#pragma unroll
                    for (int mt = 0; mt < 2; mt++)
                        mma16816(acc[mt][nt], ah[mt], bl[nt]);
#pragma unroll
                for (int nt = 0; nt < 8; nt++)
#pragma unroll
                    for (int mt = 0; mt < 2; mt++)
                        mma16816(acc[mt][nt], al[mt], bh[nt]);
            }
        }

        // ---- epilogue: bias + fp32 store ----
#pragma unroll
        for (int mt = 0; mt < 2; mt++) {
            int row0 = m0 + wm * 32 + mt * 16 + g;
#pragma unroll
            for (int nt = 0; nt < 8; nt++) {
                int col = n0 + wn * 64 + nt * 8 + tg * 2;
                float b0 = __ldg(&bias[col]), b1 = __ldg(&bias[col + 1]);
                float2 v0 = make_float2(acc[mt][nt][0] + b0, acc[mt][nt][1] + b1);
                float2 v1 = make_float2(acc[mt][nt][2] + b0, acc[mt][nt][3] + b1);
                *(float2*)&y[(size_t)row0 * Cn + col] = v0;
                *(float2*)&y[(size_t)(row0 + 8) * Cn + col] = v1;
            }
        }
#undef ISSUE
    }

    // ---- fused duration-regulator gather slice (conv1 launch only) ----
    if (outp) {
        int gid = blockIdx.y * gridDim.x + blockIdx.x;   // 0..511
        int base = gid * 256;
        for (int rr = wid; rr < 256; rr += 16) {
            int row = base + rr;
            int b2 = row >> 12;
            int f = row & (LMAX - 1);
            float4* orow = (float4*)(outp + (size_t)row * Cn);
            int total = g_total[b2];
            if (f >= total) {
                float4 z = make_float4(0.f, 0.f, 0.f, 0.f);
#pragma unroll
                for (int i = 0; i < 4; i++) orow[lane + i * 32] = z;
            } else {
                int idx = g_idx[row];
                const float4* brow = (const float4*)(batch + ((size_t)b2 * Tn + idx) * Cn);
#pragma unroll
                for (int i = 0; i < 4; i++) orow[lane + i * 32] = brow[lane + i * 32];
            }
        }
    }
}

// ---------------------------------------------------------------------------
// ReLU + LayerNorm (+optional fused Linear head). One warp per (b,t) row.
// ---------------------------------------------------------------------------
__global__ __launch_bounds__(256) void ln_relu(const float* __restrict__ y,
                                               const float* __restrict__ g,
                                               const float* __restrict__ beta,
                                               const int* __restrict__ tlen,
                                               __nv_bfloat16* __restrict__ hhi,
                                               __nv_bfloat16* __restrict__ hlo,
                                               const float* __restrict__ lw,
                                               const float* __restrict__ lb,
                                               float* __restrict__ pred)
{
    int warp = (blockIdx.x * blockDim.x + threadIdx.x) >> 5;
    int lane = threadIdx.x & 31;
    if (warp >= BT) return;
    int b = warp >> 10, t = warp & 1023;
    int len = __ldg(&tlen[b]);

    if (pred) {
        if (t >= len) { if (lane == 0) pred[warp] = 0.f; return; }
    } else {
        if (t > len) return;
    }

    const float* yr = y + (size_t)warp * Cn;
    float4 v[4];
    float s = 0.f, ss = 0.f;
#pragma unroll
    for (int i = 0; i < 4; i++) {
        v[i] = *(const float4*)&yr[(lane + i * 32) * 4];
        v[i].x = fmaxf(v[i].x, 0.f);
        v[i].y = fmaxf(v[i].y, 0.f);
        v[i].z = fmaxf(v[i].z, 0.f);
        v[i].w = fmaxf(v[i].w, 0.f);
        s  += v[i].x + v[i].y + v[i].z + v[i].w;
        ss += v[i].x * v[i].x + v[i].y * v[i].y + v[i].z * v[i].z + v[i].w * v[i].w;
    }
#pragma unroll
    for (int o = 16; o > 0; o >>= 1) {
        s  += __shfl_xor_sync(0xFFFFFFFFu, s, o);
        ss += __shfl_xor_sync(0xFFFFFFFFu, ss, o);
    }
    float mean = s * (1.f / Cn);
    float var = ss * (1.f / Cn) - mean * mean;
    float r = rsqrtf(var + 1e-5f);

    float dot = 0.f;
#pragma unroll
    for (int i = 0; i < 4; i++) {
        int c = (lane + i * 32) * 4;
        float4 o;
        o.x = (v[i].x - mean) * r * __ldg(&g[c + 0]) + __ldg(&beta[c + 0]);
        o.y = (v[i].y - mean) * r * __ldg(&g[c + 1]) + __ldg(&beta[c + 1]);
        o.z = (v[i].z - mean) * r * __ldg(&g[c + 2]) + __ldg(&beta[c + 2]);
        o.w = (v[i].w - mean) * r * __ldg(&g[c + 3]) + __ldg(&beta[c + 3]);
        if (pred) {
            float4 wv = *(const float4*)&lw[c];
            dot += o.x * wv.x + o.y * wv.y + o.z * wv.z + o.w * wv.w;
        } else {
            size_t idx = (size_t)warp * Cn + c;
            uint32_t l0, l1;
            uint32_t h0 = pack_hi(o.x, o.y, l0);
            uint32_t h1 = pack_hi(o.z, o.w, l1);
            *(uint2*)&hhi[idx] = make_uint2(h0, h1);
            *(uint2*)&hlo[idx] = make_uint2(l0, l1);
        }
    }
    if (pred) {
#pragma unroll
        for (int o = 16; o > 0; o >>= 1)
            dot += __shfl_xor_sync(0xFFFFFFFFu, dot, o);
        if (lane == 0) pred[warp] = dot + __ldg(&lb[0]);
    }
}

// ---------------------------------------------------------------------------
// Per-batch masked durations, zero-total fallback, inclusive cumsum, totals,
// AND frame->token LUT scatter.
// ---------------------------------------------------------------------------
__global__ void durations_k(const int* __restrict__ dur,
                            const int* __restrict__ tlen,
                            float* __restrict__ mel_len_out)
{
    __shared__ int sd[Tn];
    int b = blockIdx.x, t = threadIdx.x;
    int len = tlen[b];
    int valid = (t < len) ? 1 : 0;
    int d = valid ? dur[b * Tn + t] : 0;

    sd[t] = d;
    __syncthreads();
#pragma unroll
    for (int o = 512; o > 0; o >>= 1) {
        if (t < o) sd[t] += sd[t + o];
        __syncthreads();
    }
    int total = sd[0];
    __syncthreads();

    if (total == 0) d = valid;

    sd[t] = d;
    __syncthreads();
    for (int o = 1; o < Tn; o <<= 1) {
        int v = (t >= o) ? sd[t - o] : 0;
        __syncthreads();
        sd[t] += v;
        __syncthreads();
    }
    int cum = sd[t];
    int start = cum - d;
    for (int f = start; f < cum; f++)
        g_idx[b * LMAX + f] = t;
    if (t == Tn - 1) {
        g_total[b] = cum;
        mel_len_out[b] = (float)cum;
    }
}

// ---------------------------------------------------------------------------
extern "C" void kernel_launch(void* const* d_in, const int* in_sizes, int n_in,
                              void* d_out, int out_size)
{
    const float* batch = (const float*)d_in[0];
    const int*   tlen  = (const int*)d_in[1];
    const int*   dur   = (const int*)d_in[3];
    const float* w1  = (const float*)d_in[4];
    const float* b1  = (const float*)d_in[5];
    const float* g1  = (const float*)d_in[6];
    const float* be1 = (const float*)d_in[7];
    const float* w2  = (const float*)d_in[8];
    const float* b2  = (const float*)d_in[9];
    const float* g2  = (const float*)d_in[10];
    const float* be2 = (const float*)d_in[11];
    const float* lw  = (const float*)d_in[12];
    const float* lb  = (const float*)d_in[13];

    float* out = (float*)d_out;
    float* out_pb = out;
    float* out_ml = out + (size_t)Bsz * LMAX * Cn;
    float* out_pd = out_ml + Bsz;

    float *buf1;
    __nv_bfloat16 *xhi, *xlo, *whi, *wlo;
    cudaGetSymbolAddress((void**)&buf1, g_buf1);
    cudaGetSymbolAddress((void**)&xhi, g_xhi);
    cudaGetSymbolAddress((void**)&xlo, g_xlo);
    cudaGetSymbolAddress((void**)&whi, g_whi);
    cudaGetSymbolAddress((void**)&wlo, g_wlo);

    cudaFuncSetAttribute(conv_tc, cudaFuncAttributeMaxDynamicSharedMemorySize, SMEM_TOT);

    dim3 gg(Cn / BN, BT / BM);   // (2, 256)
    const size_t WSZ = (size_t)3 * 512 * 512;

    durations_k<<<Bsz, Tn>>>(dur, tlen, out_ml);
    prep<<<XBLK + WBLK, 256>>>(batch, tlen, w1, w2, xhi, xlo);

    // conv1 + fused gather (each CTA also writes its 256-row gather slice)
    conv_tc<<<gg, 512, SMEM_TOT>>>(xhi, xlo, whi, wlo, b1, tlen, 0, buf1,
                                   batch, out_pb);
    ln_relu<<<BT / 8, 256>>>(buf1, g1, be1, tlen, xhi, xlo, nullptr, nullptr, nullptr);

    conv_tc<<<gg, 512, SMEM_TOT>>>(xhi, xlo, whi + WSZ, wlo + WSZ, b2, tlen, -1, buf1,
                                   nullptr, nullptr);
    ln_relu<<<BT / 8, 256>>>(buf1, g2, be2, tlen, nullptr, nullptr, lw, lb, out_pd);
}

// round 13
// speedup vs baseline: 2.2280x; 2.2280x over previous
#include <cuda_runtime.h>
#include <cuda_fp16.h>
#include <math.h>
#include <cstdint>

#define Bsz   32
#define Tn    1024
#define Cn    512
#define LMAX  4096
#define BT    (Bsz * Tn)

// ---------------------------------------------------------------------------
// Scratch (allocation-free rule: device globals)
// ---------------------------------------------------------------------------
__device__ float  g_buf1[(size_t)BT * Cn];            // conv output
__device__ __half g_xh[(size_t)BT * Cn];              // activation fp16
__device__ __half g_wh[2][3 * 512 * 512];             // weights fp16, [conv][tap][n][ci]
__device__ int    g_idx[Bsz * LMAX];                  // frame -> token LUT
__device__ int    g_total[Bsz];

// ---------------------------------------------------------------------------
// Helpers
// ---------------------------------------------------------------------------
__device__ __forceinline__ uint32_t smem_u32(const void* p) {
    uint32_t a;
    asm("{ .reg .u64 t; cvta.to.shared.u64 t, %1; cvt.u32.u64 %0, t; }" : "=r"(a) : "l"(p));
    return a;
}
__device__ __forceinline__ void cp_async16(uint32_t dst, const void* src) {
    asm volatile("cp.async.ca.shared.global [%0], [%1], 16;" :: "r"(dst), "l"(src) : "memory");
}
__device__ __forceinline__ void cp_async16z(uint32_t dst, const void* src, int sz) {
    asm volatile("cp.async.ca.shared.global [%0], [%1], 16, %2;" :: "r"(dst), "l"(src), "r"(sz) : "memory");
}
#define CP_COMMIT() asm volatile("cp.async.commit_group;" ::: "memory")
#define CP_WAIT0()  asm volatile("cp.async.wait_group 0;" ::: "memory")
#define CP_WAIT1()  asm volatile("cp.async.wait_group 1;" ::: "memory")

__device__ __forceinline__ void ldsm_x4(uint32_t* r, uint32_t addr) {
    asm volatile("ldmatrix.sync.aligned.m8n8.x4.shared.b16 {%0,%1,%2,%3}, [%4];"
        : "=r"(r[0]), "=r"(r[1]), "=r"(r[2]), "=r"(r[3]) : "r"(addr));
}

__device__ __forceinline__ void mma16816h(float* d, const uint32_t* a, const uint32_t* b) {
    asm volatile(
        "mma.sync.aligned.m16n8k16.row.col.f32.f16.f16.f32 "
        "{%0,%1,%2,%3}, {%4,%5,%6,%7}, {%8,%9}, {%0,%1,%2,%3};"
        : "+f"(d[0]), "+f"(d[1]), "+f"(d[2]), "+f"(d[3])
        : "r"(a[0]), "r"(a[1]), "r"(a[2]), "r"(a[3]), "r"(b[0]), "r"(b[1]));
}

__device__ __forceinline__ uint32_t pack_h2(float a, float b) {
    __half2 h = __floats2half2_rn(a, b);
    return *reinterpret_cast<uint32_t*>(&h);
}

// ---------------------------------------------------------------------------
// Combined prep: blocks [0, XBLK) convert activations to fp16,
// [XBLK, XBLK+WBLK) convert both conv weights to fp16 ([tap][n][ci] layout).
// ---------------------------------------------------------------------------
#define XBLK 8192                     // BT*Cn / (256*8)
#define WBLK 6144                     // 2*3*512*512 / 256
__global__ __launch_bounds__(256) void prep(const float* __restrict__ x,
                                            const int* __restrict__ tlen,
                                            const float* __restrict__ w1s,
                                            const float* __restrict__ w2s,
                                            __half* __restrict__ xh)
{
    if (blockIdx.x < XBLK) {
        size_t i = ((size_t)blockIdx.x * 256 + threadIdx.x) * 8;
        int row = (int)(i >> 9);
        int b = row >> 10, t = row & 1023;
        if (t > __ldg(&tlen[b]) + 2) return;
        float4 v0 = *(const float4*)(x + i);
        float4 v1 = *(const float4*)(x + i + 4);
        uint4 o;
        o.x = pack_h2(v0.x, v0.y);
        o.y = pack_h2(v0.z, v0.w);
        o.z = pack_h2(v1.x, v1.y);
        o.w = pack_h2(v1.z, v1.w);
        *(uint4*)(xh + i) = o;
    } else {
        int i = (blockIdx.x - XBLK) * 256 + threadIdx.x;
        int cv = i >= 512 * 512 * 3;
        int j = cv ? i - 512 * 512 * 3 : i;
        const float* w = cv ? w2s : w1s;
        int n = j / 1536, rem = j % 1536, ci = rem / 3, k = rem % 3;
        size_t o = ((size_t)k * 512 + n) * 512 + ci;
        g_wh[cv][o] = __float2half(w[j]);
    }
}

// ---------------------------------------------------------------------------
// Conv1d(512,512,K=3,SAME) via ldmatrix + HMMA fp16 single-pass.
// Block tile 128x256, BK=64 (stride-144 smem rows, conflict-free), 512 thr.
// 3-stage cp.async pipeline, 24 chunks (tap-major).
// Tiles with t0 > len + skip_off are skipped (outputs only feed masked data).
// ---------------------------------------------------------------------------
#define BM 128
#define BN 256
#define NCH 24
#define AST 18432                    // 128 rows * 144B
#define BST 36864                    // 256 rows * 144B
#define STAGE (AST + BST)            // 55296
#define SMEM_TOT (3 * STAGE)         // 165888

__global__ __launch_bounds__(512) void conv_tc(const __half* __restrict__ xh,
                                               const __half* __restrict__ wh,
                                               const float* __restrict__ bias,
                                               const int* __restrict__ tlen,
                                               int skip_off,
                                               float* __restrict__ y)
{
    extern __shared__ char smc[];
    const int tid = threadIdx.x, wid = tid >> 5, lane = tid & 31;
    const int wm = wid & 3, wn = wid >> 2;
    const int g = lane >> 2, tg = lane & 3;
    const int n0 = blockIdx.x * BN;
    const int m0 = blockIdx.y * BM;
    const int b = m0 >> 10, t0 = m0 & 1023;

    const int len = __ldg(&tlen[b]);
    if (t0 > len + skip_off) return;

    float acc[2][8][4];
#pragma unroll
    for (int mt = 0; mt < 2; mt++)
#pragma unroll
        for (int nt = 0; nt < 8; nt++)
#pragma unroll
            for (int j = 0; j < 4; j++) acc[mt][nt][j] = 0.f;

#define ISSUE(ch, stg) do {                                                           \
    int tau = (ch) >> 3, ci0 = ((ch) & 7) * 64;                                       \
    char* S = smc + (stg) * STAGE;                                                    \
    _Pragma("unroll")                                                                 \
    for (int q = 0; q < 2; q++) {                                                     \
        int t = tid + q * 512;                                                        \
        int row = t >> 3, seg = t & 7;                                                \
        int tt = t0 + row + tau - 1;                                                  \
        int tc = tt < 0 ? 0 : (tt > 1023 ? 1023 : tt);                                \
        const __half* src = xh + ((size_t)(b << 10) + tc) * 512 + ci0 + seg * 8;      \
        int sz = ((unsigned)tt < 1024u) ? 16 : 0;                                     \
        cp_async16z(smem_u32(S + row * 144 + seg * 16), src, sz);                     \
    }                                                                                 \
    _Pragma("unroll")                                                                 \
    for (int q = 0; q < 4; q++) {                                                     \
        int t = tid + q * 512;                                                        \
        int row = t >> 3, seg = t & 7;                                                \
        const __half* src = wh + ((size_t)(tau * 512 + n0 + row)) * 512 + ci0 + seg * 8; \
        cp_async16(smem_u32(S + AST + row * 144 + seg * 16), src);                    \
    }                                                                                 \
    CP_COMMIT();                                                                      \
} while (0)

    ISSUE(0, 0);
    ISSUE(1, 1);

    const uint32_t a_row = (uint32_t)(wm * 32 + (lane & 15));
    const uint32_t a_koff = (uint32_t)((lane >> 4) * 16);
    const uint32_t b_row = (uint32_t)(wn * 64 + (lane & 7) + ((lane >> 4) * 8));
    const uint32_t b_koff = (uint32_t)(((lane >> 3) & 1) * 16);

    for (int ch = 0; ch < NCH; ch++) {
        if (ch == NCH - 1) { CP_WAIT0(); } else { CP_WAIT1(); }
        __syncthreads();
        if (ch + 2 < NCH) ISSUE(ch + 2, (ch + 2) % 3);

        char* S = smc + (ch % 3) * STAGE;
        char* Ah = S;
        char* Bh = S + AST;

#pragma unroll
        for (int kk2 = 0; kk2 < 4; kk2++) {
            const int kb = kk2 * 32;
            uint32_t ah[2][4], bh[8][2];
#pragma unroll
            for (int mt = 0; mt < 2; mt++) {
                uint32_t off = (a_row + mt * 16) * 144 + a_koff + kb;
                ldsm_x4(ah[mt], smem_u32(Ah + off));
            }
#pragma unroll
            for (int p = 0; p < 4; p++) {
                uint32_t off = (b_row + p * 16) * 144 + b_koff + kb;
                uint32_t r[4];
                ldsm_x4(r, smem_u32(Bh + off));
                bh[2 * p][0] = r[0]; bh[2 * p][1] = r[1];
                bh[2 * p + 1][0] = r[2]; bh[2 * p + 1][1] = r[3];
            }
#pragma unroll
            for (int nt = 0; nt < 8; nt++)
#pragma unroll
                for (int mt = 0; mt < 2; mt++)
                    mma16816h(acc[mt][nt], ah[mt], bh[nt]);
        }
    }

    // ---- epilogue: bias + fp32 store ----
#pragma unroll
    for (int mt = 0; mt < 2; mt++) {
        int row0 = m0 + wm * 32 + mt * 16 + g;
#pragma unroll
        for (int nt = 0; nt < 8; nt++) {
            int col = n0 + wn * 64 + nt * 8 + tg * 2;
            float b0 = __ldg(&bias[col]), b1 = __ldg(&bias[col + 1]);
            float2 v0 = make_float2(acc[mt][nt][0] + b0, acc[mt][nt][1] + b1);
            float2 v1 = make_float2(acc[mt][nt][2] + b0, acc[mt][nt][3] + b1);
            *(float2*)&y[(size_t)row0 * Cn + col] = v0;
            *(float2*)&y[(size_t)(row0 + 8) * Cn + col] = v1;
        }
    }
#undef ISSUE
}

// ---------------------------------------------------------------------------
// ReLU + LayerNorm (+optional fused Linear head). One warp per (b,t) row.
// Split path: writes fp16 LN output for rows t <= len only.
// Pred path: computes dot(LN, lw)+lb with mask (t >= len -> 0).
// ---------------------------------------------------------------------------
__global__ __launch_bounds__(256) void ln_relu(const float* __restrict__ y,
                                               const float* __restrict__ g,
                                               const float* __restrict__ beta,
                                               const int* __restrict__ tlen,
                                               __half* __restrict__ hh,
                                               const float* __restrict__ lw,
                                               const float* __restrict__ lb,
                                               float* __restrict__ pred)
{
    int warp = (blockIdx.x * blockDim.x + threadIdx.x) >> 5;
    int lane = threadIdx.x & 31;
    if (warp >= BT) return;
    int b = warp >> 10, t = warp & 1023;
    int len = __ldg(&tlen[b]);

    if (pred) {
        if (t >= len) { if (lane == 0) pred[warp] = 0.f; return; }
    } else {
        if (t > len) return;
    }

    const float* yr = y + (size_t)warp * Cn;
    float4 v[4];
    float s = 0.f, ss = 0.f;
#pragma unroll
    for (int i = 0; i < 4; i++) {
        v[i] = *(const float4*)&yr[(lane + i * 32) * 4];
        v[i].x = fmaxf(v[i].x, 0.f);
        v[i].y = fmaxf(v[i].y, 0.f);
        v[i].z = fmaxf(v[i].z, 0.f);
        v[i].w = fmaxf(v[i].w, 0.f);
        s  += v[i].x + v[i].y + v[i].z + v[i].w;
        ss += v[i].x * v[i].x + v[i].y * v[i].y + v[i].z * v[i].z + v[i].w * v[i].w;
    }
#pragma unroll
    for (int o = 16; o > 0; o >>= 1) {
        s  += __shfl_xor_sync(0xFFFFFFFFu, s, o);
        ss += __shfl_xor_sync(0xFFFFFFFFu, ss, o);
    }
    float mean = s * (1.f / Cn);
    float var = ss * (1.f / Cn) - mean * mean;
    float r = rsqrtf(var + 1e-5f);

    float dot = 0.f;
#pragma unroll
    for (int i = 0; i < 4; i++) {
        int c = (lane + i * 32) * 4;
        float4 o;
        o.x = (v[i].x - mean) * r * __ldg(&g[c + 0]) + __ldg(&beta[c + 0]);
        o.y = (v[i].y - mean) * r * __ldg(&g[c + 1]) + __ldg(&beta[c + 1]);
        o.z = (v[i].z - mean) * r * __ldg(&g[c + 2]) + __ldg(&beta[c + 2]);
        o.w = (v[i].w - mean) * r * __ldg(&g[c + 3]) + __ldg(&beta[c + 3]);
        if (pred) {
            float4 wv = *(const float4*)&lw[c];
            dot += o.x * wv.x + o.y * wv.y + o.z * wv.z + o.w * wv.w;
        } else {
            uint2 pk;
            pk.x = pack_h2(o.x, o.y);
            pk.y = pack_h2(o.z, o.w);
            *(uint2*)&hh[(size_t)warp * Cn + c] = pk;
        }
    }
    if (pred) {
#pragma unroll
        for (int o = 16; o > 0; o >>= 1)
            dot += __shfl_xor_sync(0xFFFFFFFFu, dot, o);
        if (lane == 0) pred[warp] = dot + __ldg(&lb[0]);
    }
}

// ---------------------------------------------------------------------------
// Per-batch masked durations, zero-total fallback, inclusive cumsum, totals,
// AND frame->token LUT scatter.
// ---------------------------------------------------------------------------
__global__ void durations_k(const int* __restrict__ dur,
                            const int* __restrict__ tlen,
                            float* __restrict__ mel_len_out)
{
    __shared__ int sd[Tn];
    int b = blockIdx.x, t = threadIdx.x;
    int len = tlen[b];
    int valid = (t < len) ? 1 : 0;
    int d = valid ? dur[b * Tn + t] : 0;

    sd[t] = d;
    __syncthreads();
#pragma unroll
    for (int o = 512; o > 0; o >>= 1) {
        if (t < o) sd[t] += sd[t + o];
        __syncthreads();
    }
    int total = sd[0];
    __syncthreads();

    if (total == 0) d = valid;

    sd[t] = d;
    __syncthreads();
    for (int o = 1; o < Tn; o <<= 1) {
        int v = (t >= o) ? sd[t - o] : 0;
        __syncthreads();
        sd[t] += v;
        __syncthreads();
    }
    int cum = sd[t];
    int start = cum - d;
    for (int f = start; f < cum; f++)
        g_idx[b * LMAX + f] = t;
    if (t == Tn - 1) {
        g_total[b] = cum;
        mel_len_out[b] = (float)cum;
    }
}

// ---------------------------------------------------------------------------
// Duration regulation gather via LUT. One warp per output frame row.
// ---------------------------------------------------------------------------
__global__ __launch_bounds__(256) void gather_k(const float* __restrict__ batch,
                                                float* __restrict__ out)
{
    int row = (blockIdx.x * blockDim.x + threadIdx.x) >> 5;
    int lane = threadIdx.x & 31;
    if (row >= Bsz * LMAX) return;
    int b = row >> 12;
    int f = row & (LMAX - 1);

    float4* orow = (float4*)(out + (size_t)row * Cn);
    int total = g_total[b];
    if (f >= total) {
        float4 z = make_float4(0.f, 0.f, 0.f, 0.f);
#pragma unroll
        for (int i = 0; i < 4; i++) orow[lane + i * 32] = z;
        return;
    }
    int idx = g_idx[row];
    const float4* brow = (const float4*)(batch + ((size_t)b * Tn + idx) * Cn);
#pragma unroll
    for (int i = 0; i < 4; i++) orow[lane + i * 32] = brow[lane + i * 32];
}

// ---------------------------------------------------------------------------
extern "C" void kernel_launch(void* const* d_in, const int* in_sizes, int n_in,
                              void* d_out, int out_size)
{
    const float* batch = (const float*)d_in[0];
    const int*   tlen  = (const int*)d_in[1];
    const int*   dur   = (const int*)d_in[3];
    const float* w1  = (const float*)d_in[4];
    const float* b1  = (const float*)d_in[5];
    const float* g1  = (const float*)d_in[6];
    const float* be1 = (const float*)d_in[7];
    const float* w2  = (const float*)d_in[8];
    const float* b2  = (const float*)d_in[9];
    const float* g2  = (const float*)d_in[10];
    const float* be2 = (const float*)d_in[11];
    const float* lw  = (const float*)d_in[12];
    const float* lb  = (const float*)d_in[13];

    float* out = (float*)d_out;
    float* out_pb = out;
    float* out_ml = out + (size_t)Bsz * LMAX * Cn;
    float* out_pd = out_ml + Bsz;

    float* buf1;
    __half *xh, *wh;
    cudaGetSymbolAddress((void**)&buf1, g_buf1);
    cudaGetSymbolAddress((void**)&xh, g_xh);
    cudaGetSymbolAddress((void**)&wh, g_wh);

    cudaFuncSetAttribute(conv_tc, cudaFuncAttributeMaxDynamicSharedMemorySize, SMEM_TOT);

    dim3 gg(Cn / BN, BT / BM);   // (2, 256)
    const size_t WSZ = (size_t)3 * 512 * 512;

    durations_k<<<Bsz, Tn>>>(dur, tlen, out_ml);
    prep<<<XBLK + WBLK, 256>>>(batch, tlen, w1, w2, xh);

    conv_tc<<<gg, 512, SMEM_TOT>>>(xh, wh, b1, tlen, 0, buf1);
    ln_relu<<<BT / 8, 256>>>(buf1, g1, be1, tlen, xh, nullptr, nullptr, nullptr);

    conv_tc<<<gg, 512, SMEM_TOT>>>(xh, wh + WSZ, b2, tlen, -1, buf1);
    ln_relu<<<BT / 8, 256>>>(buf1, g2, be2, tlen, nullptr, lw, lb, out_pd);

    gather_k<<<(Bsz * LMAX) / 8, 256>>>(batch, out_pb);
}